// round 13
// baseline (speedup 1.0000x reference)
#include <cuda_runtime.h>
#include <math.h>
#include <string.h>

#define PI_D 3.141592653589793238462643383279502884

typedef unsigned long long ull;

// ---------------- packed table layout (floats) ----------------
// OFF_D    : D interleaved [chunk5][idx716][kc4]          : 14320
// OFF_W    : quadrature * wigner d_{m,0}, m>=0 packed     : 3300
// OFF_KFT  : kernel FT basis float2 [s][g]                : 1200
// OFF_E60  : float2 [a][m]                                : 1200
// OFF_E4Q  : float4 [vp-1][q] (ex,ex,ey,ey)               : 360
// OFF_E20P : float4 [p][uu-1] (2ex,2ex,-2ey,-2ey)         : 360
#define OFF_D    0
#define OFF_W    14320
#define OFF_KFT  17620
#define OFF_E60  18820
#define OFF_E4Q  20020
#define OFF_E20P 20380
#define TAB_LEN  20740

#define SIGN2 0x8000000080000000ULL

__device__ __align__(16) float TAB_d[TAB_LEN];
__device__ float2 FHAT_d[512 * 2 * 100];

// OFFU[l] = sum_{j<l} (j+1)(2j+1)  (u>=0 packed layout)
__constant__ int OFFU_c[11] = {0, 1, 7, 22, 50, 95, 161, 252, 372, 525, 715};
static const int OFFU_h[11] = {0, 1, 7, 22, 50, 95, 161, 252, 372, 525, 715};

// S-phase pairs (u,vp) packed u*16+vp, sorted by lmin=max(u,vp) ascending
// (loop trip = 10-lmin, descending) so warps have uniform trip counts.
__constant__ unsigned char SP_c[90] = {
    // lmin=1
    1, 17,
    // lmin=2
    2, 18, 33, 34,
    // lmin=3
    3, 19, 35, 49, 50, 51,
    // lmin=4
    4, 20, 36, 52, 65, 66, 67, 68,
    // lmin=5
    5, 21, 37, 53, 69, 81, 82, 83, 84, 85,
    // lmin=6
    6, 22, 38, 54, 70, 86, 97, 98, 99, 100, 101, 102,
    // lmin=7
    7, 23, 39, 55, 71, 87, 103, 113, 114, 115, 116, 117, 118, 119,
    // lmin=8
    8, 24, 40, 56, 72, 88, 104, 120, 129, 130, 131, 132, 133, 134, 135, 136,
    // lmin=9
    9, 25, 41, 57, 73, 89, 105, 121, 137, 145, 146, 147, 148, 149, 150, 151, 152, 153
};

// ---------------- packed f32x2 PTX helpers ----------------
#define FMA2(d, a, b, c) \
    asm("fma.rn.f32x2 %0, %1, %2, %3;" : "=l"(d) : "l"(a), "l"(b), "l"(c))
#define ADD2(d, a, b) \
    asm("add.rn.f32x2 %0, %1, %2;" : "=l"(d) : "l"(a), "l"(b))
#define PACK2(d, lo, hi) \
    asm("mov.b64 %0, {%1, %2};" : "=l"(d) : "r"(__float_as_uint(lo)), "r"(__float_as_uint(hi)))
#define UNPACK2(lo, hi, v) \
    do { unsigned _ulo, _uhi; \
         asm("mov.b64 {%0, %1}, %2;" : "=r"(_ulo), "=r"(_uhi) : "l"(v)); \
         lo = __uint_as_float(_ulo); hi = __uint_as_float(_uhi); } while (0)

// ================= HOST table generation (capture time only) =================
static double h_fact[19];

static double h_wig(int l, int mp, int m, double cb, double sb) {
    double pref = sqrt(h_fact[l + m] * h_fact[l - m] * h_fact[l + mp] * h_fact[l - mp]);
    int smin = (m - mp) > 0 ? (m - mp) : 0;
    int smax = (l + m) < (l - mp) ? (l + m) : (l - mp);
    double tot = 0.0;
    for (int s = smin; s <= smax; s++) {
        double den = h_fact[l + m - s] * h_fact[s] * h_fact[mp - m + s] * h_fact[l - mp - s];
        double t = pow(cb, (double)(2 * l + m - mp - 2 * s)) * pow(sb, (double)(mp - m + 2 * s)) / den;
        tot += ((mp - m + s) & 1) ? -t : t;
    }
    return pref * tot;
}

static float host_tab[TAB_LEN];

static void h_build_tables() {
    memset(host_tab, 0, sizeof(host_tab));
    h_fact[0] = 1.0;
    for (int j = 1; j < 19; j++) h_fact[j] = h_fact[j - 1] * (double)j;

    double wq[60];
    for (int j = 0; j < 60; j++) {
        double beta = PI_D * (2 * j + 1) / 120.0;
        double s = 0.0;
        for (int k = 0; k < 30; k++)
            s += sin((double)(2 * j + 1) * (2 * k + 1) * PI_D / 120.0) / (double)(2 * k + 1);
        wq[j] = (2.0 / 30.0) * sin(beta) * s;
    }

    // D interleaved: [chunk][idx][kc], k = chunk*4 + kc
    for (int k = 0; k < 20; k++) {
        int c = k / 4, kc = k % 4;
        double beta = PI_D * (2 * k + 1) / 40.0;
        double cb = cos(beta * 0.5), sb = sin(beta * 0.5);
        for (int l = 0; l < 10; l++) {
            int L = 2 * l + 1;
            for (int u = 0; u <= l; u++)
                for (int vi = 0; vi < L; vi++) {
                    int idx = OFFU_h[l] + u * L + vi;
                    host_tab[OFF_D + c * 2864 + idx * 4 + kc] =
                        (float)(h_wig(l, u, vi - l, cb, sb) * (double)L);
                }
        }
    }

    for (int k = 0; k < 60; k++) {
        double beta = PI_D * (2 * k + 1) / 120.0;
        double cb = cos(beta * 0.5), sb = sin(beta * 0.5);
        for (int l = 0; l < 10; l++)
            for (int m = 0; m <= l; m++)
                host_tab[OFF_W + k * 55 + l * (l + 1) / 2 + m] =
                    (float)(wq[k] * h_wig(l, m, 0, cb, sb));
    }

    {
        double beta = PI_D / 160.0;
        double cb = cos(beta * 0.5), sb = sin(beta * 0.5);
        for (int l = 0; l < 10; l++)
            for (int m = -l; m <= l; m++) {
                int s = l * l + l + m;
                double d0 = h_wig(l, m, 0, cb, sb);
                for (int g = 0; g < 6; g++) {
                    double ga = 2.0 * PI_D * (double)g / 6.0;
                    host_tab[OFF_KFT + (s * 6 + g) * 2 + 0] = (float)(d0 * cos((double)m * ga));
                    host_tab[OFF_KFT + (s * 6 + g) * 2 + 1] = (float)(-d0 * sin((double)m * ga));
                }
            }
    }

    for (int a = 0; a < 60; a++)
        for (int m = 0; m < 10; m++) {
            double th = -2.0 * PI_D * (double)a * (double)m / 60.0;
            host_tab[OFF_E60 + (a * 10 + m) * 2 + 0] = (float)cos(th);
            host_tab[OFF_E60 + (a * 10 + m) * 2 + 1] = (float)sin(th);
        }

    for (int vp = 1; vp <= 9; vp++)
        for (int q = 0; q < 10; q++) {
            double th = 2.0 * PI_D * (double)q * (double)vp / 20.0;
            float ex = (float)cos(th), ey = (float)sin(th);
            int base = OFF_E4Q + ((vp - 1) * 10 + q) * 4;
            host_tab[base + 0] = ex; host_tab[base + 1] = ex;
            host_tab[base + 2] = ey; host_tab[base + 3] = ey;
        }

    for (int p = 0; p < 10; p++)
        for (int uu = 1; uu <= 9; uu++) {
            double th = 2.0 * PI_D * (double)p * (double)uu / 20.0;
            float ex = (float)(2.0 * cos(th)), ey = (float)(2.0 * sin(th));
            int base = OFF_E20P + (p * 9 + uu - 1) * 4;
            host_tab[base + 0] = ex;  host_tab[base + 1] = ex;
            host_tab[base + 2] = -ey; host_tab[base + 3] = -ey;
        }
}

// ================= stage 1: fhat[b][i][s] ====================================
__global__ __launch_bounds__(128) void k_fhat(const float* __restrict__ x) {
    __shared__ __align__(16) float  xsT[60 * 61];  // [a][k], pitch 61
    __shared__ __align__(16) float2 xf2[600];      // [k][m]
    __shared__ __align__(16) float2 e60[600];      // [a][m]
    int bi = blockIdx.x;   // b*2 + i
    const float* xp = x + (size_t)bi * 3600;
    const float2* E60g = (const float2*)(TAB_d + OFF_E60);
    for (int t = threadIdx.x; t < 3600; t += 128) {
        int k = t / 60, a = t % 60;
        xsT[a * 61 + k] = xp[t];
    }
    for (int t = threadIdx.x; t < 600; t += 128) e60[t] = E60g[t];
    __syncthreads();
    for (int t = threadIdx.x; t < 300; t += 128) {
        int mp = t / 60, k = t % 60;
        ull acc0 = 0, acc1 = 0;
        #pragma unroll 4
        for (int a = 0; a < 60; a++) {
            float xv = xsT[a * 61 + k];
            ull xv2; PACK2(xv2, xv, xv);
            const ulonglong2 e2 = *reinterpret_cast<const ulonglong2*>(&e60[a * 10 + 2 * mp]);
            FMA2(acc0, xv2, e2.x, acc0);
            FMA2(acc1, xv2, e2.y, acc1);
        }
        float r0, i0, r1, i1;
        UNPACK2(r0, i0, acc0);
        UNPACK2(r1, i1, acc1);
        xf2[k * 10 + 2 * mp]     = make_float2(r0, i0);
        xf2[k * 10 + 2 * mp + 1] = make_float2(r1, i1);
    }
    __syncthreads();
    {
        int t = threadIdx.x;
        int sp = t >> 1;
        if (sp > 54) sp = 54;
        int half = t & 1;
        int l = 0;
        #pragma unroll
        for (int j = 1; j < 10; j++) if (j * (j + 1) / 2 <= sp) l = j;
        int m = sp - l * (l + 1) / 2;
        float re = 0.f, im = 0.f;
        int k0 = half * 30;
        #pragma unroll 5
        for (int k = k0; k < k0 + 30; k++) {
            float w = TAB_d[OFF_W + k * 55 + sp];
            float2 v = xf2[k * 10 + m];
            re += w * v.x; im += w * v.y;
        }
        re += __shfl_xor_sync(0xFFFFFFFFu, re, 1);
        im += __shfl_xor_sync(0xFFFFFFFFu, im, 1);
        if (half == 0 && t < 110) {
            FHAT_d[bi * 100 + l * l + l + m] = make_float2(re, im);
            if (m > 0) {
                float sg = (m & 1) ? -1.f : 1.f;
                FHAT_d[bi * 100 + l * l + l - m] = make_float2(sg * re, -sg * im);
            }
        }
    }
}

// ================= stage 3: main — sorted S items, float4 G cells ============
#define KCH 4   // 5 chunks of 4 k's

// shared layout (bytes):
//   Dbuf float[716*4] interleaved [idx][kc]           : 0     .. 11456
//   ST4  float4[360]  [(vp-1)*40 + u*4 + kc]          : 11456 .. 17216
//   S0   float2[40]   (u*4+kc)                        : 17216 .. 17536
//   e4q  float4[90]                                   : 17536 .. 18976
//   e20p float4[90]                                   : 18976 .. 20416
//   zs   float2[715]                                  : 20416 .. 26136 (pad 26144)
//   union @26144: A: Fs float2[200], Ys float2[200] @27744
//                 B: Gre float[800] @26144, Gim float[800] @29344
//                    G cell layout: [(kh*10+u)*10+qp]*4 + comp,
//                    comp = 2*j + (q&1); qp = q>>1 (d-results at qp+5)
#define SM_BYTES 32544

__global__ __launch_bounds__(256, 6) void k_main(const float* __restrict__ kern,
                                                 const float* __restrict__ bias,
                                                 float* __restrict__ out) {
    __shared__ __align__(16) char SM[SM_BYTES];
    float*  Dbuf_s = (float*)(SM);
    float4* ST4_s  = (float4*)(SM + 11456);
    float2* S0_s   = (float2*)(SM + 17216);
    float4* e4q_s  = (float4*)(SM + 17536);
    float4* e20p_s = (float4*)(SM + 18976);
    float2* zs     = (float2*)(SM + 20416);
    float2* Fs     = (float2*)(SM + 26144);
    float2* Ys     = (float2*)(SM + 27744);
    float*  Gre_s  = (float*)(SM + 26144);
    float*  Gim_s  = (float*)(SM + 29344);

    int b = blockIdx.x, o = blockIdx.y;
    int tid = threadIdx.x;

    // D chunk copy: chunk C -> 716 float4 ([idx][kc] interleaved)
    #define D_LOAD(C, T0, NT)                                                    \
    {   const float4* Dg = (const float4*)(TAB_d + OFF_D) + (C) * 716;           \
        float4* Db = (float4*)Dbuf_s;                                            \
        for (int t = (T0); t < 716; t += (NT)) Db[t] = Dg[t];                    \
    }

    // ---- initial loads (+ D chunk 0) ----
    for (int t = tid; t < 200; t += 256) Fs[t] = FHAT_d[b * 200 + t];
    {
        const float2* KFT = (const float2*)(TAB_d + OFF_KFT);
        const float SC = (float)(1.0 / sqrt(6.0 * 2.0 * 10000.0 / 900.0));
        for (int t = tid; t < 200; t += 256) {
            int i = t / 100, s = t % 100;
            float re = 0.f, im = 0.f;
            #pragma unroll
            for (int g = 0; g < 6; g++) {
                float kv = kern[(i * 5 + o) * 6 + g];
                float2 kf = KFT[s * 6 + g];
                re += kv * kf.x; im += kv * kf.y;
            }
            Ys[t] = make_float2(re * SC, -im * SC);
        }
    }
    {
        const float4* EQ = (const float4*)(TAB_d + OFF_E4Q);
        const float4* EP = (const float4*)(TAB_d + OFF_E20P);
        if (tid < 90) e4q_s[tid] = EQ[tid];
        else if (tid < 180) e20p_s[tid - 90] = EP[tid - 90];
    }
    D_LOAD(0, tid, 256)
    __syncthreads();

    // ---- z-phase ----
    for (int t = tid; t < 715; t += 256) {
        int l = 0;
        #pragma unroll
        for (int j = 1; j < 10; j++) if (OFFU_c[j] <= t) l = j;
        int jj = t - OFFU_c[l]; int L = 2 * l + 1;
        int u = jj / L, vi = jj % L;
        int su = l * l + l + u, sv = l * l + vi;
        float2 f0 = Fs[su], f1 = Fs[100 + su], y0 = Ys[sv], y1 = Ys[100 + sv];
        float re = f0.x * y0.x - f0.y * y0.y + f1.x * y1.x - f1.y * y1.y;
        float im = f0.x * y0.y + f0.y * y0.x + f1.x * y1.y + f1.y * y1.x;
        zs[t] = make_float2(re, im);
    }
    __syncthreads();

    float bo = bias[o];
    ull bo2; PACK2(bo2, bo, bo);
    float* outp = out + ((size_t)(b * 5 + o)) * 8000;

    // S-phase over chunk in Dbuf; items sorted by loop trip (SP_c)
    #define S_PHASE()                                                            \
    for (int it = tid; it < 400; it += 256) {                                    \
        if (it < 40) {                                                           \
            int u = it / 4, kc = it % 4;                                         \
            ull acc = 0;                                                         \
            for (int l = u; l < 10; l++) {                                       \
                int idx = OFFU_c[l] + u * (2 * l + 1) + l;                       \
                float d = Dbuf_s[idx * 4 + kc];                                  \
                ull d2; PACK2(d2, d, d);                                         \
                ull z2 = *reinterpret_cast<const ull*>(&zs[idx]);                \
                FMA2(acc, d2, z2, acc);                                          \
            }                                                                    \
            *reinterpret_cast<ull*>(&S0_s[u * 4 + kc]) = acc;                    \
        } else {                                                                 \
            int it2 = it - 40;                                                   \
            int uv = SP_c[it2 >> 2];                                             \
            int kc = it2 & 3;                                                    \
            int u = uv >> 4, vp = uv & 15;                                       \
            int lmin = u > vp ? u : vp;                                          \
            ull accP = 0, accM = 0;                                              \
            for (int l = lmin; l < 10; l++) {                                    \
                int base = OFFU_c[l] + u * (2 * l + 1) + l;                      \
                float dp = Dbuf_s[(base + vp) * 4 + kc];                         \
                float dm = Dbuf_s[(base - vp) * 4 + kc];                         \
                ull dp2, dm2; PACK2(dp2, dp, dp); PACK2(dm2, dm, dm);            \
                ull zp = *reinterpret_cast<const ull*>(&zs[base + vp]);          \
                ull zm = *reinterpret_cast<const ull*>(&zs[base - vp]);          \
                FMA2(accP, dp2, zp, accP);                                       \
                FMA2(accM, dm2, zm, accM);                                       \
            }                                                                    \
            float pr, pi, mr, mi;                                                \
            UNPACK2(pr, pi, accP);                                               \
            UNPACK2(mr, mi, accM);                                               \
            ST4_s[(vp - 1) * 40 + u * 4 + kc] =                                  \
                make_float4(pr + mr, pi + mi, mi - pi, pr - mr);                 \
        }                                                                        \
    }

    S_PHASE()
    __syncthreads();

    for (int c = 0; c < 5; c++) {
        int k0 = c * KCH;
        // ---- G-phase (threads <200) || D-load chunk c+1 (threads >=200) ----
        if (tid < 200) {
            int kh = tid / 100, r = tid % 100;
            int q = r % 10, u = r / 10;
            int kc0 = kh * 2;
            ull acc_e[2], acc_o[2];
            #pragma unroll
            for (int j = 0; j < 2; j++) {
                acc_e[j] = *reinterpret_cast<const ull*>(&S0_s[u * 4 + kc0 + j]);
                acc_o[j] = 0ull;
            }
            const ulonglong2* STu = (const ulonglong2*)ST4_s;
            #pragma unroll
            for (int vp = 1; vp <= 9; vp++) {
                const ulonglong2 e2 =
                    *reinterpret_cast<const ulonglong2*>(&e4q_s[(vp - 1) * 10 + q]);
                int sbase = (vp - 1) * 40 + u * 4 + kc0;
                #pragma unroll
                for (int j = 0; j < 2; j++) {
                    ulonglong2 st = STu[sbase + j];
                    if (vp & 1) {
                        FMA2(acc_o[j], e2.x, st.x, acc_o[j]);
                        FMA2(acc_o[j], e2.y, st.y, acc_o[j]);
                    } else {
                        FMA2(acc_e[j], e2.x, st.x, acc_e[j]);
                        FMA2(acc_e[j], e2.y, st.y, acc_e[j]);
                    }
                }
            }
            // store into float4 G cells: comp = 2*j + (q&1), qp = q>>1 (+5 for q+10)
            #pragma unroll
            for (int j = 0; j < 2; j++) {
                int cbase = ((kh * 10 + u) * 10 + (q >> 1)) * 4 + 2 * j + (q & 1);
                ull s, d;
                ADD2(s, acc_e[j], acc_o[j]);
                ull no = acc_o[j] ^ SIGN2;
                ADD2(d, acc_e[j], no);
                float gr, gi;
                UNPACK2(gr, gi, s);
                Gre_s[cbase] = gr;
                Gim_s[cbase] = gi;
                UNPACK2(gr, gi, d);
                Gre_s[cbase + 20] = gr;   // qp + 5 cells = +20 floats
                Gim_s[cbase + 20] = gi;
            }
        } else if (c < 4) {
            D_LOAD(c + 1, tid - 200, 56)
        }
        __syncthreads();
        // ---- out-phase (threads <200) then S(c+1) (all threads) ----
        if (tid < 200) {
            int kh = tid / 100, r = tid % 100;
            int p = r / 10, qp = r % 10;
            int qof = qp * 2;
            ull acc_e[2], acc_o[2];
            {
                const ulonglong2 g0 =
                    *reinterpret_cast<const ulonglong2*>(&Gre_s[(kh * 100 + qp) * 4]);
                ADD2(acc_e[0], bo2, g0.x);
                ADD2(acc_e[1], bo2, g0.y);
                acc_o[0] = 0ull; acc_o[1] = 0ull;
            }
            #pragma unroll
            for (int uu = 1; uu <= 9; uu++) {
                const ulonglong2 e2 =
                    *reinterpret_cast<const ulonglong2*>(&e20p_s[p * 9 + uu - 1]);
                int gb = (kh * 100 + uu * 10 + qp) * 4;
                const ulonglong2 g4r = *reinterpret_cast<const ulonglong2*>(&Gre_s[gb]);
                const ulonglong2 g4i = *reinterpret_cast<const ulonglong2*>(&Gim_s[gb]);
                if (uu & 1) {
                    FMA2(acc_o[0], e2.x, g4r.x, acc_o[0]);
                    FMA2(acc_o[0], e2.y, g4i.x, acc_o[0]);
                    FMA2(acc_o[1], e2.x, g4r.y, acc_o[1]);
                    FMA2(acc_o[1], e2.y, g4i.y, acc_o[1]);
                } else {
                    FMA2(acc_e[0], e2.x, g4r.x, acc_e[0]);
                    FMA2(acc_e[0], e2.y, g4i.x, acc_e[0]);
                    FMA2(acc_e[1], e2.x, g4r.y, acc_e[1]);
                    FMA2(acc_e[1], e2.y, g4i.y, acc_e[1]);
                }
            }
            #pragma unroll
            for (int j = 0; j < 2; j++) {
                int kc = kh * 2 + j;
                ull s, d;
                ADD2(s, acc_e[j], acc_o[j]);
                ull no = acc_o[j] ^ SIGN2;
                ADD2(d, acc_e[j], no);
                *reinterpret_cast<ull*>(&outp[(k0 + kc) * 400 + p * 20 + qof]) = s;
                *reinterpret_cast<ull*>(&outp[(k0 + kc) * 400 + (p + 10) * 20 + qof]) = d;
            }
        }
        // S(c+1): reads Dbuf (filled during G-phase; barrier above orders it)
        if (c < 4) {
            S_PHASE()
        }
        __syncthreads();
    }
    #undef S_PHASE
    #undef D_LOAD
}

// ================= launch ====================================================
extern "C" void kernel_launch(void* const* d_in, const int* in_sizes, int n_in,
                              void* d_out, int out_size) {
    const float* x    = (const float*)d_in[0];  // (512, 2, 60, 60)
    const float* kern = (const float*)d_in[1];  // (2, 5, 6)
    const float* bias = (const float*)d_in[2];  // (5)
    float* out = (float*)d_out;                 // (512, 5, 20, 20, 20)

    h_build_tables();
    cudaMemcpyToSymbolAsync(TAB_d, host_tab, sizeof(float) * TAB_LEN, 0,
                            cudaMemcpyHostToDevice, 0);

    k_fhat<<<1024, 128>>>(x);
    dim3 g(512, 5);
    k_main<<<g, 256>>>(kern, bias, out);
}

// round 16
// speedup vs baseline: 1.1604x; 1.1604x over previous
#include <cuda_runtime.h>
#include <math.h>
#include <string.h>

#define PI_D 3.141592653589793238462643383279502884

typedef unsigned long long ull;

// ---------------- packed table layout (floats) ----------------
// OFF_D    : D interleaved [chunk5][idx716][kc4]          : 14320
// OFF_W    : quadrature * wigner d_{m,0}, m>=0 packed     : 3300
// OFF_KFT  : kernel FT basis float2 [s][g]                : 1200
// OFF_E60  : float2 [a][m]                                : 1200
// OFF_W4   : float4 [q] (wx,wx,wy,wy), w=e^{i pi q/10}    : 40
#define OFF_D    0
#define OFF_W    14320
#define OFF_KFT  17620
#define OFF_E60  18820
#define OFF_W4   20020
#define TAB_LEN  20060

#define SIGN2 0x8000000080000000ULL

__device__ __align__(16) float TAB_d[TAB_LEN];
__device__ float2 FHAT_d[512 * 2 * 100];

// OFFU[l] = sum_{j<l} (j+1)(2j+1)  (u>=0 packed layout)
__constant__ int OFFU_c[11] = {0, 1, 7, 22, 50, 95, 161, 252, 372, 525, 715};
static const int OFFU_h[11] = {0, 1, 7, 22, 50, 95, 161, 252, 372, 525, 715};

// S-phase pairs (u,vp) packed u*16+vp, sorted by lmin=max(u,vp) ascending
__constant__ unsigned char SP_c[90] = {
    1, 17,
    2, 18, 33, 34,
    3, 19, 35, 49, 50, 51,
    4, 20, 36, 52, 65, 66, 67, 68,
    5, 21, 37, 53, 69, 81, 82, 83, 84, 85,
    6, 22, 38, 54, 70, 86, 97, 98, 99, 100, 101, 102,
    7, 23, 39, 55, 71, 87, 103, 113, 114, 115, 116, 117, 118, 119,
    8, 24, 40, 56, 72, 88, 104, 120, 129, 130, 131, 132, 133, 134, 135, 136,
    9, 25, 41, 57, 73, 89, 105, 121, 137, 145, 146, 147, 148, 149, 150, 151, 152, 153
};

// ---------------- packed f32x2 PTX helpers ----------------
#define FMA2(d, a, b, c) \
    asm("fma.rn.f32x2 %0, %1, %2, %3;" : "=l"(d) : "l"(a), "l"(b), "l"(c))
#define ADD2(d, a, b) \
    asm("add.rn.f32x2 %0, %1, %2;" : "=l"(d) : "l"(a), "l"(b))
#define PACK2(d, lo, hi) \
    asm("mov.b64 %0, {%1, %2};" : "=l"(d) : "r"(__float_as_uint(lo)), "r"(__float_as_uint(hi)))
#define UNPACK2(lo, hi, v) \
    do { unsigned _ulo, _uhi; \
         asm("mov.b64 {%0, %1}, %2;" : "=r"(_ulo), "=r"(_uhi) : "l"(v)); \
         lo = __uint_as_float(_ulo); hi = __uint_as_float(_uhi); } while (0)

// ================= HOST table generation (capture time only) =================
static double h_fact[19];

static double h_wig(int l, int mp, int m, double cb, double sb) {
    double pref = sqrt(h_fact[l + m] * h_fact[l - m] * h_fact[l + mp] * h_fact[l - mp]);
    int smin = (m - mp) > 0 ? (m - mp) : 0;
    int smax = (l + m) < (l - mp) ? (l + m) : (l - mp);
    double tot = 0.0;
    for (int s = smin; s <= smax; s++) {
        double den = h_fact[l + m - s] * h_fact[s] * h_fact[mp - m + s] * h_fact[l - mp - s];
        double t = pow(cb, (double)(2 * l + m - mp - 2 * s)) * pow(sb, (double)(mp - m + 2 * s)) / den;
        tot += ((mp - m + s) & 1) ? -t : t;
    }
    return pref * tot;
}

static float host_tab[TAB_LEN];

static void h_build_tables() {
    memset(host_tab, 0, sizeof(host_tab));
    h_fact[0] = 1.0;
    for (int j = 1; j < 19; j++) h_fact[j] = h_fact[j - 1] * (double)j;

    double wq[60];
    for (int j = 0; j < 60; j++) {
        double beta = PI_D * (2 * j + 1) / 120.0;
        double s = 0.0;
        for (int k = 0; k < 30; k++)
            s += sin((double)(2 * j + 1) * (2 * k + 1) * PI_D / 120.0) / (double)(2 * k + 1);
        wq[j] = (2.0 / 30.0) * sin(beta) * s;
    }

    // D interleaved: [chunk][idx][kc], k = chunk*4 + kc
    for (int k = 0; k < 20; k++) {
        int c = k / 4, kc = k % 4;
        double beta = PI_D * (2 * k + 1) / 40.0;
        double cb = cos(beta * 0.5), sb = sin(beta * 0.5);
        for (int l = 0; l < 10; l++) {
            int L = 2 * l + 1;
            for (int u = 0; u <= l; u++)
                for (int vi = 0; vi < L; vi++) {
                    int idx = OFFU_h[l] + u * L + vi;
                    host_tab[OFF_D + c * 2864 + idx * 4 + kc] =
                        (float)(h_wig(l, u, vi - l, cb, sb) * (double)L);
                }
        }
    }

    for (int k = 0; k < 60; k++) {
        double beta = PI_D * (2 * k + 1) / 120.0;
        double cb = cos(beta * 0.5), sb = sin(beta * 0.5);
        for (int l = 0; l < 10; l++)
            for (int m = 0; m <= l; m++)
                host_tab[OFF_W + k * 55 + l * (l + 1) / 2 + m] =
                    (float)(wq[k] * h_wig(l, m, 0, cb, sb));
    }

    {
        double beta = PI_D / 160.0;
        double cb = cos(beta * 0.5), sb = sin(beta * 0.5);
        for (int l = 0; l < 10; l++)
            for (int m = -l; m <= l; m++) {
                int s = l * l + l + m;
                double d0 = h_wig(l, m, 0, cb, sb);
                for (int g = 0; g < 6; g++) {
                    double ga = 2.0 * PI_D * (double)g / 6.0;
                    host_tab[OFF_KFT + (s * 6 + g) * 2 + 0] = (float)(d0 * cos((double)m * ga));
                    host_tab[OFF_KFT + (s * 6 + g) * 2 + 1] = (float)(-d0 * sin((double)m * ga));
                }
            }
    }

    for (int a = 0; a < 60; a++)
        for (int m = 0; m < 10; m++) {
            double th = -2.0 * PI_D * (double)a * (double)m / 60.0;
            host_tab[OFF_E60 + (a * 10 + m) * 2 + 0] = (float)cos(th);
            host_tab[OFF_E60 + (a * 10 + m) * 2 + 1] = (float)sin(th);
        }

    // W4[q] = (wx, wx, wy, wy), w = e^{+i pi q / 10}
    for (int q = 0; q < 10; q++) {
        double th = PI_D * (double)q / 10.0;
        float wx = (float)cos(th), wy = (float)sin(th);
        host_tab[OFF_W4 + q * 4 + 0] = wx;
        host_tab[OFF_W4 + q * 4 + 1] = wx;
        host_tab[OFF_W4 + q * 4 + 2] = wy;
        host_tab[OFF_W4 + q * 4 + 3] = wy;
    }
}

// ================= stage 1: fhat[b][i][s] ====================================
__global__ __launch_bounds__(128) void k_fhat(const float* __restrict__ x) {
    __shared__ __align__(16) float  xsT[60 * 61];  // [a][k], pitch 61
    __shared__ __align__(16) float2 xf2[600];      // [k][m]
    __shared__ __align__(16) float2 e60[600];      // [a][m]
    int bi = blockIdx.x;   // b*2 + i
    const float* xp = x + (size_t)bi * 3600;
    const float2* E60g = (const float2*)(TAB_d + OFF_E60);
    for (int t = threadIdx.x; t < 3600; t += 128) {
        int k = t / 60, a = t % 60;
        xsT[a * 61 + k] = xp[t];
    }
    for (int t = threadIdx.x; t < 600; t += 128) e60[t] = E60g[t];
    __syncthreads();
    for (int t = threadIdx.x; t < 300; t += 128) {
        int mp = t / 60, k = t % 60;
        ull acc0 = 0, acc1 = 0;
        #pragma unroll 4
        for (int a = 0; a < 60; a++) {
            float xv = xsT[a * 61 + k];
            ull xv2; PACK2(xv2, xv, xv);
            const ulonglong2 e2 = *reinterpret_cast<const ulonglong2*>(&e60[a * 10 + 2 * mp]);
            FMA2(acc0, xv2, e2.x, acc0);
            FMA2(acc1, xv2, e2.y, acc1);
        }
        float r0, i0, r1, i1;
        UNPACK2(r0, i0, acc0);
        UNPACK2(r1, i1, acc1);
        xf2[k * 10 + 2 * mp]     = make_float2(r0, i0);
        xf2[k * 10 + 2 * mp + 1] = make_float2(r1, i1);
    }
    __syncthreads();
    {
        int t = threadIdx.x;
        int sp = t >> 1;
        if (sp > 54) sp = 54;
        int half = t & 1;
        int l = 0;
        #pragma unroll
        for (int j = 1; j < 10; j++) if (j * (j + 1) / 2 <= sp) l = j;
        int m = sp - l * (l + 1) / 2;
        float re = 0.f, im = 0.f;
        int k0 = half * 30;
        #pragma unroll 5
        for (int k = k0; k < k0 + 30; k++) {
            float w = TAB_d[OFF_W + k * 55 + sp];
            float2 v = xf2[k * 10 + m];
            re += w * v.x; im += w * v.y;
        }
        re += __shfl_xor_sync(0xFFFFFFFFu, re, 1);
        im += __shfl_xor_sync(0xFFFFFFFFu, im, 1);
        if (half == 0 && t < 110) {
            FHAT_d[bi * 100 + l * l + l + m] = make_float2(re, im);
            if (m > 0) {
                float sg = (m & 1) ? -1.f : 1.f;
                FHAT_d[bi * 100 + l * l + l - m] = make_float2(sg * re, -sg * im);
            }
        }
    }
}

// ================= stage 3: main — twiddle recurrence in registers ===========
#define KCH 4   // 5 chunks of 4 k's

// shared layout (bytes):
//   Dbuf float[716*4] interleaved [idx][kc]           : 0     .. 11456
//   ST4  float4[360]  [(vp-1)*40 + u*4 + kc]          : 11456 .. 17216
//   S0   float2[40]   (u*4+kc)                        : 17216 .. 17536
//   w4   float4[10]   (wx,wx,wy,wy)                   : 17536 .. 17696
//   zs   float2[715]                                  : 17696 .. 23416 (pad 23424)
//   union @23424: A: Fs float2[200], Ys float2[200] @25024
//                 B: Gre float[800] @23424, Gim float[800] @26624
//                    G cell layout: [(kh*10+u)*10+qp]*4 + comp
#define SM_BYTES 29824

__global__ __launch_bounds__(256, 6) void k_main(const float* __restrict__ kern,
                                                 const float* __restrict__ bias,
                                                 float* __restrict__ out) {
    __shared__ __align__(16) char SM[SM_BYTES];
    float*  Dbuf_s = (float*)(SM);
    float4* ST4_s  = (float4*)(SM + 11456);
    float2* S0_s   = (float2*)(SM + 17216);
    float4* w4_s   = (float4*)(SM + 17536);
    float2* zs     = (float2*)(SM + 17696);
    float2* Fs     = (float2*)(SM + 23424);
    float2* Ys     = (float2*)(SM + 25024);
    float*  Gre_s  = (float*)(SM + 23424);
    float*  Gim_s  = (float*)(SM + 26624);

    int b = blockIdx.x, o = blockIdx.y;
    int tid = threadIdx.x;

    #define D_LOAD(C, T0, NT)                                                    \
    {   const float4* Dg = (const float4*)(TAB_d + OFF_D) + (C) * 716;           \
        float4* Db = (float4*)Dbuf_s;                                            \
        for (int t = (T0); t < 716; t += (NT)) Db[t] = Dg[t];                    \
    }

    // ---- initial loads (+ D chunk 0) ----
    for (int t = tid; t < 200; t += 256) Fs[t] = FHAT_d[b * 200 + t];
    {
        const float2* KFT = (const float2*)(TAB_d + OFF_KFT);
        const float SC = (float)(1.0 / sqrt(6.0 * 2.0 * 10000.0 / 900.0));
        for (int t = tid; t < 200; t += 256) {
            int i = t / 100, s = t % 100;
            float re = 0.f, im = 0.f;
            #pragma unroll
            for (int g = 0; g < 6; g++) {
                float kv = kern[(i * 5 + o) * 6 + g];
                float2 kf = KFT[s * 6 + g];
                re += kv * kf.x; im += kv * kf.y;
            }
            Ys[t] = make_float2(re * SC, -im * SC);
        }
    }
    if (tid < 10) w4_s[tid] = ((const float4*)(TAB_d + OFF_W4))[tid];
    D_LOAD(0, tid, 256)
    __syncthreads();

    // ---- z-phase ----
    for (int t = tid; t < 715; t += 256) {
        int l = 0;
        #pragma unroll
        for (int j = 1; j < 10; j++) if (OFFU_c[j] <= t) l = j;
        int jj = t - OFFU_c[l]; int L = 2 * l + 1;
        int u = jj / L, vi = jj % L;
        int su = l * l + l + u, sv = l * l + vi;
        float2 f0 = Fs[su], f1 = Fs[100 + su], y0 = Ys[sv], y1 = Ys[100 + sv];
        float re = f0.x * y0.x - f0.y * y0.y + f1.x * y1.x - f1.y * y1.y;
        float im = f0.x * y0.y + f0.y * y0.x + f1.x * y1.y + f1.y * y1.x;
        zs[t] = make_float2(re, im);
    }
    __syncthreads();

    float bo = bias[o];
    ull bo2; PACK2(bo2, bo, bo);
    float* outp = out + ((size_t)(b * 5 + o)) * 8000;

    // S-phase over chunk in Dbuf; items sorted by loop trip (SP_c)
    #define S_PHASE()                                                            \
    for (int it = tid; it < 400; it += 256) {                                    \
        if (it < 40) {                                                           \
            int u = it / 4, kc = it % 4;                                         \
            ull acc = 0;                                                         \
            for (int l = u; l < 10; l++) {                                       \
                int idx = OFFU_c[l] + u * (2 * l + 1) + l;                       \
                float d = Dbuf_s[idx * 4 + kc];                                  \
                ull d2; PACK2(d2, d, d);                                         \
                ull z2 = *reinterpret_cast<const ull*>(&zs[idx]);                \
                FMA2(acc, d2, z2, acc);                                          \
            }                                                                    \
            *reinterpret_cast<ull*>(&S0_s[u * 4 + kc]) = acc;                    \
        } else {                                                                 \
            int it2 = it - 40;                                                   \
            int uv = SP_c[it2 >> 2];                                             \
            int kc = it2 & 3;                                                    \
            int u = uv >> 4, vp = uv & 15;                                       \
            int lmin = u > vp ? u : vp;                                          \
            ull accP = 0, accM = 0;                                              \
            for (int l = lmin; l < 10; l++) {                                    \
                int base = OFFU_c[l] + u * (2 * l + 1) + l;                      \
                float dp = Dbuf_s[(base + vp) * 4 + kc];                         \
                float dm = Dbuf_s[(base - vp) * 4 + kc];                         \
                ull dp2, dm2; PACK2(dp2, dp, dp); PACK2(dm2, dm, dm);            \
                ull zp = *reinterpret_cast<const ull*>(&zs[base + vp]);          \
                ull zm = *reinterpret_cast<const ull*>(&zs[base - vp]);          \
                FMA2(accP, dp2, zp, accP);                                       \
                FMA2(accM, dm2, zm, accM);                                       \
            }                                                                    \
            float pr, pi, mr, mi;                                                \
            UNPACK2(pr, pi, accP);                                               \
            UNPACK2(mr, mi, accM);                                               \
            ST4_s[(vp - 1) * 40 + u * 4 + kc] =                                  \
                make_float4(pr + mr, pi + mi, mi - pi, pr - mr);                 \
        }                                                                        \
    }

    S_PHASE()
    __syncthreads();

    for (int c = 0; c < 5; c++) {
        int k0 = c * KCH;
        // ---- G-phase (threads <200): twiddle recurrence over vp ----
        if (tid < 200) {
            int kh = tid / 100, r = tid % 100;
            int q = r % 10, u = r / 10;
            int kc0 = kh * 2;
            float4 wv = w4_s[q];          // (wx,wx,wy,wy)
            float wx = wv.x, wy = wv.z;
            float ex = wx, ey = wy;       // e(vp=1)
            ull acc_e[2], acc_o[2];
            #pragma unroll
            for (int j = 0; j < 2; j++) {
                acc_e[j] = *reinterpret_cast<const ull*>(&S0_s[u * 4 + kc0 + j]);
                acc_o[j] = 0ull;
            }
            const ulonglong2* STu = (const ulonglong2*)ST4_s;
            #pragma unroll
            for (int vp = 1; vp <= 9; vp++) {
                ull exx, eyy;
                PACK2(exx, ex, ex);
                PACK2(eyy, ey, ey);
                int sbase = (vp - 1) * 40 + u * 4 + kc0;
                #pragma unroll
                for (int j = 0; j < 2; j++) {
                    ulonglong2 st = STu[sbase + j];
                    if (vp & 1) {
                        FMA2(acc_o[j], exx, st.x, acc_o[j]);
                        FMA2(acc_o[j], eyy, st.y, acc_o[j]);
                    } else {
                        FMA2(acc_e[j], exx, st.x, acc_e[j]);
                        FMA2(acc_e[j], eyy, st.y, acc_e[j]);
                    }
                }
                float nx = ex * wx - ey * wy;
                ey = ex * wy + ey * wx;
                ex = nx;
            }
            #pragma unroll
            for (int j = 0; j < 2; j++) {
                int cbase = ((kh * 10 + u) * 10 + (q >> 1)) * 4 + 2 * j + (q & 1);
                ull s, d;
                ADD2(s, acc_e[j], acc_o[j]);
                ull no = acc_o[j] ^ SIGN2;
                ADD2(d, acc_e[j], no);
                float gr, gi;
                UNPACK2(gr, gi, s);
                Gre_s[cbase] = gr;
                Gim_s[cbase] = gi;
                UNPACK2(gr, gi, d);
                Gre_s[cbase + 20] = gr;
                Gim_s[cbase + 20] = gi;
            }
        } else if (c < 4) {
            D_LOAD(c + 1, tid - 200, 56)
        }
        __syncthreads();
        // ---- out-phase (threads <200): twiddle recurrence over uu ----
        if (tid < 200) {
            int kh = tid / 100, r = tid % 100;
            int p = r / 10, qp = r % 10;
            int qof = qp * 2;
            float4 wv = w4_s[p];
            float wx = wv.x, wy = wv.z;
            float gx = 2.f * wx, gy = 2.f * wy;   // 2*e(uu=1)
            ull acc_e[2], acc_o[2];
            {
                const ulonglong2 g0 =
                    *reinterpret_cast<const ulonglong2*>(&Gre_s[(kh * 100 + qp) * 4]);
                ADD2(acc_e[0], bo2, g0.x);
                ADD2(acc_e[1], bo2, g0.y);
                acc_o[0] = 0ull; acc_o[1] = 0ull;
            }
            #pragma unroll
            for (int uu = 1; uu <= 9; uu++) {
                ull e2x, e2y;
                PACK2(e2x, gx, gx);
                float ngy = -gy;
                PACK2(e2y, ngy, ngy);
                int gb = (kh * 100 + uu * 10 + qp) * 4;
                const ulonglong2 g4r = *reinterpret_cast<const ulonglong2*>(&Gre_s[gb]);
                const ulonglong2 g4i = *reinterpret_cast<const ulonglong2*>(&Gim_s[gb]);
                if (uu & 1) {
                    FMA2(acc_o[0], e2x, g4r.x, acc_o[0]);
                    FMA2(acc_o[0], e2y, g4i.x, acc_o[0]);
                    FMA2(acc_o[1], e2x, g4r.y, acc_o[1]);
                    FMA2(acc_o[1], e2y, g4i.y, acc_o[1]);
                } else {
                    FMA2(acc_e[0], e2x, g4r.x, acc_e[0]);
                    FMA2(acc_e[0], e2y, g4i.x, acc_e[0]);
                    FMA2(acc_e[1], e2x, g4r.y, acc_e[1]);
                    FMA2(acc_e[1], e2y, g4i.y, acc_e[1]);
                }
                float nx = gx * wx - gy * wy;
                gy = gx * wy + gy * wx;
                gx = nx;
            }
            #pragma unroll
            for (int j = 0; j < 2; j++) {
                int kc = kh * 2 + j;
                ull s, d;
                ADD2(s, acc_e[j], acc_o[j]);
                ull no = acc_o[j] ^ SIGN2;
                ADD2(d, acc_e[j], no);
                *reinterpret_cast<ull*>(&outp[(k0 + kc) * 400 + p * 20 + qof]) = s;
                *reinterpret_cast<ull*>(&outp[(k0 + kc) * 400 + (p + 10) * 20 + qof]) = d;
            }
        }
        // S(c+1): reads Dbuf (filled during G-phase; barrier above orders it)
        if (c < 4) {
            S_PHASE()
        }
        __syncthreads();
    }
    #undef S_PHASE
    #undef D_LOAD
}

// ================= launch ====================================================
extern "C" void kernel_launch(void* const* d_in, const int* in_sizes, int n_in,
                              void* d_out, int out_size) {
    const float* x    = (const float*)d_in[0];  // (512, 2, 60, 60)
    const float* kern = (const float*)d_in[1];  // (2, 5, 6)
    const float* bias = (const float*)d_in[2];  // (5)
    float* out = (float*)d_out;                 // (512, 5, 20, 20, 20)

    h_build_tables();
    cudaMemcpyToSymbolAsync(TAB_d, host_tab, sizeof(float) * TAB_LEN, 0,
                            cudaMemcpyHostToDevice, 0);

    k_fhat<<<1024, 128>>>(x);
    dim3 g(512, 5);
    k_main<<<g, 256>>>(kern, bias, out);
}

// round 17
// speedup vs baseline: 1.1980x; 1.0324x over previous
#include <cuda_runtime.h>
#include <math.h>
#include <string.h>

#define PI_D 3.141592653589793238462643383279502884

typedef unsigned long long ull;

// ---------------- packed table layout (floats) ----------------
// OFF_D    : per chunk (2864 floats): [0,2640) pair floats2 (dp,dm) idx (pp*4+kc)
//            [2640,2860) D0 [t55*4+kc], [2860,2864) pad     : 5*2864 = 14320
// OFF_W    : quadrature * wigner d_{m,0}, m>=0 packed       : 3300
// OFF_KFT  : kernel FT basis float2 [s][g]                  : 1200
// OFF_E60  : float2 [a][m]                                  : 1200
// OFF_W4   : float4 [q] (wx,wx,wy,wy), w=e^{i pi q/10}      : 40
#define OFF_D    0
#define OFF_W    14320
#define OFF_KFT  17620
#define OFF_E60  18820
#define OFF_W4   20020
#define TAB_LEN  20060

#define SIGN2 0x8000000080000000ULL

__device__ __align__(16) float TAB_d[TAB_LEN];
__device__ float2 FHAT_d[512 * 2 * 100];

// PB[l] = pair-base: sum_{j<l} (j+1)*j  (pairs exist for l>=1)
__constant__ int PB_c[11] = {0, 0, 2, 8, 20, 40, 70, 112, 168, 240, 330};
static const int PB_h[11] = {0, 0, 2, 8, 20, 40, 70, 112, 168, 240, 330};

// S-phase pairs (u,vp) packed u*16+vp, sorted by lmin=max(u,vp) ascending
__constant__ unsigned char SP_c[90] = {
    1, 17,
    2, 18, 33, 34,
    3, 19, 35, 49, 50, 51,
    4, 20, 36, 52, 65, 66, 67, 68,
    5, 21, 37, 53, 69, 81, 82, 83, 84, 85,
    6, 22, 38, 54, 70, 86, 97, 98, 99, 100, 101, 102,
    7, 23, 39, 55, 71, 87, 103, 113, 114, 115, 116, 117, 118, 119,
    8, 24, 40, 56, 72, 88, 104, 120, 129, 130, 131, 132, 133, 134, 135, 136,
    9, 25, 41, 57, 73, 89, 105, 121, 137, 145, 146, 147, 148, 149, 150, 151, 152, 153
};

// ---------------- packed f32x2 PTX helpers ----------------
#define FMA2(d, a, b, c) \
    asm("fma.rn.f32x2 %0, %1, %2, %3;" : "=l"(d) : "l"(a), "l"(b), "l"(c))
#define ADD2(d, a, b) \
    asm("add.rn.f32x2 %0, %1, %2;" : "=l"(d) : "l"(a), "l"(b))
#define PACK2(d, lo, hi) \
    asm("mov.b64 %0, {%1, %2};" : "=l"(d) : "r"(__float_as_uint(lo)), "r"(__float_as_uint(hi)))
#define UNPACK2(lo, hi, v) \
    do { unsigned _ulo, _uhi; \
         asm("mov.b64 {%0, %1}, %2;" : "=r"(_ulo), "=r"(_uhi) : "l"(v)); \
         lo = __uint_as_float(_ulo); hi = __uint_as_float(_uhi); } while (0)

// ================= HOST table generation (capture time only) =================
static double h_fact[19];

static double h_wig(int l, int mp, int m, double cb, double sb) {
    double pref = sqrt(h_fact[l + m] * h_fact[l - m] * h_fact[l + mp] * h_fact[l - mp]);
    int smin = (m - mp) > 0 ? (m - mp) : 0;
    int smax = (l + m) < (l - mp) ? (l + m) : (l - mp);
    double tot = 0.0;
    for (int s = smin; s <= smax; s++) {
        double den = h_fact[l + m - s] * h_fact[s] * h_fact[mp - m + s] * h_fact[l - mp - s];
        double t = pow(cb, (double)(2 * l + m - mp - 2 * s)) * pow(sb, (double)(mp - m + 2 * s)) / den;
        tot += ((mp - m + s) & 1) ? -t : t;
    }
    return pref * tot;
}

static float host_tab[TAB_LEN];

static void h_build_tables() {
    memset(host_tab, 0, sizeof(host_tab));
    h_fact[0] = 1.0;
    for (int j = 1; j < 19; j++) h_fact[j] = h_fact[j - 1] * (double)j;

    double wq[60];
    for (int j = 0; j < 60; j++) {
        double beta = PI_D * (2 * j + 1) / 120.0;
        double s = 0.0;
        for (int k = 0; k < 30; k++)
            s += sin((double)(2 * j + 1) * (2 * k + 1) * PI_D / 120.0) / (double)(2 * k + 1);
        wq[j] = (2.0 / 30.0) * sin(beta) * s;
    }

    // D pair-packed per chunk: (dp,dm) float2 at (pp*4+kc), D0 at 2640 + t*4+kc
    for (int k = 0; k < 20; k++) {
        int c = k / 4, kc = k % 4;
        int base = OFF_D + c * 2864;
        double beta = PI_D * (2 * k + 1) / 40.0;
        double cb = cos(beta * 0.5), sb = sin(beta * 0.5);
        for (int l = 1; l < 10; l++)
            for (int u = 0; u <= l; u++)
                for (int vp = 1; vp <= l; vp++) {
                    int pp = PB_h[l] + u * l + vp - 1;
                    host_tab[base + (pp * 4 + kc) * 2 + 0] =
                        (float)(h_wig(l, u,  vp, cb, sb) * (double)(2 * l + 1));
                    host_tab[base + (pp * 4 + kc) * 2 + 1] =
                        (float)(h_wig(l, u, -vp, cb, sb) * (double)(2 * l + 1));
                }
        for (int l = 0; l < 10; l++)
            for (int u = 0; u <= l; u++) {
                int t = l * (l + 1) / 2 + u;
                host_tab[base + 2640 + t * 4 + kc] =
                    (float)(h_wig(l, u, 0, cb, sb) * (double)(2 * l + 1));
            }
    }

    for (int k = 0; k < 60; k++) {
        double beta = PI_D * (2 * k + 1) / 120.0;
        double cb = cos(beta * 0.5), sb = sin(beta * 0.5);
        for (int l = 0; l < 10; l++)
            for (int m = 0; m <= l; m++)
                host_tab[OFF_W + k * 55 + l * (l + 1) / 2 + m] =
                    (float)(wq[k] * h_wig(l, m, 0, cb, sb));
    }

    {
        double beta = PI_D / 160.0;
        double cb = cos(beta * 0.5), sb = sin(beta * 0.5);
        for (int l = 0; l < 10; l++)
            for (int m = -l; m <= l; m++) {
                int s = l * l + l + m;
                double d0 = h_wig(l, m, 0, cb, sb);
                for (int g = 0; g < 6; g++) {
                    double ga = 2.0 * PI_D * (double)g / 6.0;
                    host_tab[OFF_KFT + (s * 6 + g) * 2 + 0] = (float)(d0 * cos((double)m * ga));
                    host_tab[OFF_KFT + (s * 6 + g) * 2 + 1] = (float)(-d0 * sin((double)m * ga));
                }
            }
    }

    for (int a = 0; a < 60; a++)
        for (int m = 0; m < 10; m++) {
            double th = -2.0 * PI_D * (double)a * (double)m / 60.0;
            host_tab[OFF_E60 + (a * 10 + m) * 2 + 0] = (float)cos(th);
            host_tab[OFF_E60 + (a * 10 + m) * 2 + 1] = (float)sin(th);
        }

    for (int q = 0; q < 10; q++) {
        double th = PI_D * (double)q / 10.0;
        float wx = (float)cos(th), wy = (float)sin(th);
        host_tab[OFF_W4 + q * 4 + 0] = wx;
        host_tab[OFF_W4 + q * 4 + 1] = wx;
        host_tab[OFF_W4 + q * 4 + 2] = wy;
        host_tab[OFF_W4 + q * 4 + 3] = wy;
    }
}

// ================= stage 1: fhat[b][i][s] (unchanged) ========================
__global__ __launch_bounds__(128) void k_fhat(const float* __restrict__ x) {
    __shared__ __align__(16) float  xsT[60 * 61];
    __shared__ __align__(16) float2 xf2[600];
    __shared__ __align__(16) float2 e60[600];
    int bi = blockIdx.x;
    const float* xp = x + (size_t)bi * 3600;
    const float2* E60g = (const float2*)(TAB_d + OFF_E60);
    for (int t = threadIdx.x; t < 3600; t += 128) {
        int k = t / 60, a = t % 60;
        xsT[a * 61 + k] = xp[t];
    }
    for (int t = threadIdx.x; t < 600; t += 128) e60[t] = E60g[t];
    __syncthreads();
    for (int t = threadIdx.x; t < 300; t += 128) {
        int mp = t / 60, k = t % 60;
        ull acc0 = 0, acc1 = 0;
        #pragma unroll 4
        for (int a = 0; a < 60; a++) {
            float xv = xsT[a * 61 + k];
            ull xv2; PACK2(xv2, xv, xv);
            const ulonglong2 e2 = *reinterpret_cast<const ulonglong2*>(&e60[a * 10 + 2 * mp]);
            FMA2(acc0, xv2, e2.x, acc0);
            FMA2(acc1, xv2, e2.y, acc1);
        }
        float r0, i0, r1, i1;
        UNPACK2(r0, i0, acc0);
        UNPACK2(r1, i1, acc1);
        xf2[k * 10 + 2 * mp]     = make_float2(r0, i0);
        xf2[k * 10 + 2 * mp + 1] = make_float2(r1, i1);
    }
    __syncthreads();
    {
        int t = threadIdx.x;
        int sp = t >> 1;
        if (sp > 54) sp = 54;
        int half = t & 1;
        int l = 0;
        #pragma unroll
        for (int j = 1; j < 10; j++) if (j * (j + 1) / 2 <= sp) l = j;
        int m = sp - l * (l + 1) / 2;
        float re = 0.f, im = 0.f;
        int k0 = half * 30;
        #pragma unroll 5
        for (int k = k0; k < k0 + 30; k++) {
            float w = TAB_d[OFF_W + k * 55 + sp];
            float2 v = xf2[k * 10 + m];
            re += w * v.x; im += w * v.y;
        }
        re += __shfl_xor_sync(0xFFFFFFFFu, re, 1);
        im += __shfl_xor_sync(0xFFFFFFFFu, im, 1);
        if (half == 0 && t < 110) {
            FHAT_d[bi * 100 + l * l + l + m] = make_float2(re, im);
            if (m > 0) {
                float sg = (m & 1) ? -1.f : 1.f;
                FHAT_d[bi * 100 + l * l + l - m] = make_float2(sg * re, -sg * im);
            }
        }
    }
}

// ================= stage 3: main — pair-packed z & D =========================
#define KCH 4   // 5 chunks of 4 k's

// shared layout (bytes):
//   Dbuf float[2864]: pairs(float2 2640f) + D0(220f) + pad : 0 .. 11456
//   ST4  float4[360]  [(vp-1)*40 + u*4 + kc]               : 11456 .. 17216
//   S0   float2[40]   (u*4+kc)                             : 17216 .. 17536
//   w4   float4[10]   (wx,wx,wy,wy)                        : 17536 .. 17696
//   zpair float4[330] (zp.re,zp.im,zm.re,zm.im)            : 17696 .. 22976
//   z0   float2[55]                                        : 22976 .. 23416 (pad 23424)
//   union @23424: A: Fs float2[200], Ys float2[200] @25024
//                 B: Gre float[800] @23424, Gim float[800] @26624
#define SM_BYTES 29824

__global__ __launch_bounds__(256, 6) void k_main(const float* __restrict__ kern,
                                                 const float* __restrict__ bias,
                                                 float* __restrict__ out) {
    __shared__ __align__(16) char SM[SM_BYTES];
    float*  Dbuf_s  = (float*)(SM);
    float2* Dpair_s = (float2*)(SM);             // pp*4+kc
    float*  D0_s    = (float*)(SM + 10560);      // t*4+kc
    float4* ST4_s   = (float4*)(SM + 11456);
    float2* S0_s    = (float2*)(SM + 17216);
    float4* w4_s    = (float4*)(SM + 17536);
    float4* zpair_s = (float4*)(SM + 17696);
    float2* z0_s    = (float2*)(SM + 22976);
    float2* Fs      = (float2*)(SM + 23424);
    float2* Ys      = (float2*)(SM + 25024);
    float*  Gre_s   = (float*)(SM + 23424);
    float*  Gim_s   = (float*)(SM + 26624);

    int b = blockIdx.x, o = blockIdx.y;
    int tid = threadIdx.x;

    #define D_LOAD(C, T0, NT)                                                    \
    {   const float4* Dg = (const float4*)(TAB_d + OFF_D) + (C) * 716;           \
        float4* Db = (float4*)Dbuf_s;                                            \
        for (int t = (T0); t < 716; t += (NT)) Db[t] = Dg[t];                    \
    }

    // ---- initial loads (+ D chunk 0) ----
    for (int t = tid; t < 200; t += 256) Fs[t] = FHAT_d[b * 200 + t];
    {
        const float2* KFT = (const float2*)(TAB_d + OFF_KFT);
        const float SC = (float)(1.0 / sqrt(6.0 * 2.0 * 10000.0 / 900.0));
        for (int t = tid; t < 200; t += 256) {
            int i = t / 100, s = t % 100;
            float re = 0.f, im = 0.f;
            #pragma unroll
            for (int g = 0; g < 6; g++) {
                float kv = kern[(i * 5 + o) * 6 + g];
                float2 kf = KFT[s * 6 + g];
                re += kv * kf.x; im += kv * kf.y;
            }
            Ys[t] = make_float2(re * SC, -im * SC);
        }
    }
    if (tid < 10) w4_s[tid] = ((const float4*)(TAB_d + OFF_W4))[tid];
    D_LOAD(0, tid, 256)
    __syncthreads();

    // ---- z-phase: pair layout (385 items: 55 v0 + 330 pairs) ----
    for (int it = tid; it < 385; it += 256) {
        if (it < 55) {
            int t = it;
            int l = 0;
            #pragma unroll
            for (int j = 1; j < 10; j++) if (j * (j + 1) / 2 <= t) l = j;
            int u = t - l * (l + 1) / 2;
            int su = l * l + l + u, sv = l * l + l;
            float2 f0 = Fs[su], f1 = Fs[100 + su], y0 = Ys[sv], y1 = Ys[100 + sv];
            float re = f0.x * y0.x - f0.y * y0.y + f1.x * y1.x - f1.y * y1.y;
            float im = f0.x * y0.y + f0.y * y0.x + f1.x * y1.y + f1.y * y1.x;
            z0_s[t] = make_float2(re, im);
        } else {
            int pp = it - 55;
            int l = 1;
            #pragma unroll
            for (int j = 2; j < 10; j++) if (PB_c[j] <= pp) l = j;
            int r = pp - PB_c[l];
            int u = r / l, vp = r % l + 1;
            int su = l * l + l + u;
            int svp = l * l + l + vp, svm = l * l + l - vp;
            float2 f0 = Fs[su], f1 = Fs[100 + su];
            float2 yp0 = Ys[svp], yp1 = Ys[100 + svp];
            float2 ym0 = Ys[svm], ym1 = Ys[100 + svm];
            float pre = f0.x * yp0.x - f0.y * yp0.y + f1.x * yp1.x - f1.y * yp1.y;
            float pim = f0.x * yp0.y + f0.y * yp0.x + f1.x * yp1.y + f1.y * yp1.x;
            float mre = f0.x * ym0.x - f0.y * ym0.y + f1.x * ym1.x - f1.y * ym1.y;
            float mim = f0.x * ym0.y + f0.y * ym0.x + f1.x * ym1.y + f1.y * ym1.x;
            zpair_s[pp] = make_float4(pre, pim, mre, mim);
        }
    }
    __syncthreads();

    float bo = bias[o];
    ull bo2; PACK2(bo2, bo, bo);
    float* outp = out + ((size_t)(b * 5 + o)) * 8000;

    // S-phase: pair items do 2 loads/l (Dpair LDS.64 + zpair LDS.128)
    #define S_PHASE()                                                            \
    for (int it = tid; it < 400; it += 256) {                                    \
        if (it < 40) {                                                           \
            int u = it / 4, kc = it % 4;                                         \
            ull acc = 0;                                                         \
            for (int l = u; l < 10; l++) {                                       \
                int t0 = l * (l + 1) / 2 + u;                                    \
                float d = D0_s[t0 * 4 + kc];                                     \
                ull d2; PACK2(d2, d, d);                                         \
                ull z2 = *reinterpret_cast<const ull*>(&z0_s[t0]);               \
                FMA2(acc, d2, z2, acc);                                          \
            }                                                                    \
            *reinterpret_cast<ull*>(&S0_s[u * 4 + kc]) = acc;                    \
        } else {                                                                 \
            int it2 = it - 40;                                                   \
            int uv = SP_c[it2 >> 2];                                             \
            int kc = it2 & 3;                                                    \
            int u = uv >> 4, vp = uv & 15;                                       \
            int lmin = u > vp ? u : vp;                                          \
            ull accP = 0, accM = 0;                                              \
            for (int l = lmin; l < 10; l++) {                                    \
                int pp = PB_c[l] + u * l + vp - 1;                               \
                float2 dd = Dpair_s[pp * 4 + kc];                                \
                const ulonglong2 zu =                                            \
                    *reinterpret_cast<const ulonglong2*>(&zpair_s[pp]);          \
                ull dp2, dm2; PACK2(dp2, dd.x, dd.x); PACK2(dm2, dd.y, dd.y);    \
                FMA2(accP, dp2, zu.x, accP);                                     \
                FMA2(accM, dm2, zu.y, accM);                                     \
            }                                                                    \
            float pr, pi, mr, mi;                                                \
            UNPACK2(pr, pi, accP);                                               \
            UNPACK2(mr, mi, accM);                                               \
            ST4_s[(vp - 1) * 40 + u * 4 + kc] =                                  \
                make_float4(pr + mr, pi + mi, mi - pi, pr - mr);                 \
        }                                                                        \
    }

    S_PHASE()
    __syncthreads();

    for (int c = 0; c < 5; c++) {
        int k0 = c * KCH;
        // ---- G-phase (threads <200): twiddle recurrence over vp ----
        if (tid < 200) {
            int kh = tid / 100, r = tid % 100;
            int q = r % 10, u = r / 10;
            int kc0 = kh * 2;
            float4 wv = w4_s[q];
            float wx = wv.x, wy = wv.z;
            float ex = wx, ey = wy;
            ull acc_e[2], acc_o[2];
            #pragma unroll
            for (int j = 0; j < 2; j++) {
                acc_e[j] = *reinterpret_cast<const ull*>(&S0_s[u * 4 + kc0 + j]);
                acc_o[j] = 0ull;
            }
            const ulonglong2* STu = (const ulonglong2*)ST4_s;
            #pragma unroll
            for (int vp = 1; vp <= 9; vp++) {
                ull exx, eyy;
                PACK2(exx, ex, ex);
                PACK2(eyy, ey, ey);
                int sbase = (vp - 1) * 40 + u * 4 + kc0;
                #pragma unroll
                for (int j = 0; j < 2; j++) {
                    ulonglong2 st = STu[sbase + j];
                    if (vp & 1) {
                        FMA2(acc_o[j], exx, st.x, acc_o[j]);
                        FMA2(acc_o[j], eyy, st.y, acc_o[j]);
                    } else {
                        FMA2(acc_e[j], exx, st.x, acc_e[j]);
                        FMA2(acc_e[j], eyy, st.y, acc_e[j]);
                    }
                }
                float nx = ex * wx - ey * wy;
                ey = ex * wy + ey * wx;
                ex = nx;
            }
            #pragma unroll
            for (int j = 0; j < 2; j++) {
                int cbase = ((kh * 10 + u) * 10 + (q >> 1)) * 4 + 2 * j + (q & 1);
                ull s, d;
                ADD2(s, acc_e[j], acc_o[j]);
                ull no = acc_o[j] ^ SIGN2;
                ADD2(d, acc_e[j], no);
                float gr, gi;
                UNPACK2(gr, gi, s);
                Gre_s[cbase] = gr;
                Gim_s[cbase] = gi;
                UNPACK2(gr, gi, d);
                Gre_s[cbase + 20] = gr;
                Gim_s[cbase + 20] = gi;
            }
        } else if (c < 4) {
            D_LOAD(c + 1, tid - 200, 56)
        }
        __syncthreads();
        // ---- out-phase (threads <200): twiddle recurrence over uu ----
        if (tid < 200) {
            int kh = tid / 100, r = tid % 100;
            int p = r / 10, qp = r % 10;
            int qof = qp * 2;
            float4 wv = w4_s[p];
            float wx = wv.x, wy = wv.z;
            float gx = 2.f * wx, gy = 2.f * wy;
            ull acc_e[2], acc_o[2];
            {
                const ulonglong2 g0 =
                    *reinterpret_cast<const ulonglong2*>(&Gre_s[(kh * 100 + qp) * 4]);
                ADD2(acc_e[0], bo2, g0.x);
                ADD2(acc_e[1], bo2, g0.y);
                acc_o[0] = 0ull; acc_o[1] = 0ull;
            }
            #pragma unroll
            for (int uu = 1; uu <= 9; uu++) {
                ull e2x, e2y;
                PACK2(e2x, gx, gx);
                float ngy = -gy;
                PACK2(e2y, ngy, ngy);
                int gb = (kh * 100 + uu * 10 + qp) * 4;
                const ulonglong2 g4r = *reinterpret_cast<const ulonglong2*>(&Gre_s[gb]);
                const ulonglong2 g4i = *reinterpret_cast<const ulonglong2*>(&Gim_s[gb]);
                if (uu & 1) {
                    FMA2(acc_o[0], e2x, g4r.x, acc_o[0]);
                    FMA2(acc_o[0], e2y, g4i.x, acc_o[0]);
                    FMA2(acc_o[1], e2x, g4r.y, acc_o[1]);
                    FMA2(acc_o[1], e2y, g4i.y, acc_o[1]);
                } else {
                    FMA2(acc_e[0], e2x, g4r.x, acc_e[0]);
                    FMA2(acc_e[0], e2y, g4i.x, acc_e[0]);
                    FMA2(acc_e[1], e2x, g4r.y, acc_e[1]);
                    FMA2(acc_e[1], e2y, g4i.y, acc_e[1]);
                }
                float nx = gx * wx - gy * wy;
                gy = gx * wy + gy * wx;
                gx = nx;
            }
            #pragma unroll
            for (int j = 0; j < 2; j++) {
                int kc = kh * 2 + j;
                ull s, d;
                ADD2(s, acc_e[j], acc_o[j]);
                ull no = acc_o[j] ^ SIGN2;
                ADD2(d, acc_e[j], no);
                *reinterpret_cast<ull*>(&outp[(k0 + kc) * 400 + p * 20 + qof]) = s;
                *reinterpret_cast<ull*>(&outp[(k0 + kc) * 400 + (p + 10) * 20 + qof]) = d;
            }
        }
        // S(c+1): reads Dbuf (filled during G-phase; barrier above orders it)
        if (c < 4) {
            S_PHASE()
        }
        __syncthreads();
    }
    #undef S_PHASE
    #undef D_LOAD
}

// ================= launch ====================================================
extern "C" void kernel_launch(void* const* d_in, const int* in_sizes, int n_in,
                              void* d_out, int out_size) {
    const float* x    = (const float*)d_in[0];  // (512, 2, 60, 60)
    const float* kern = (const float*)d_in[1];  // (2, 5, 6)
    const float* bias = (const float*)d_in[2];  // (5)
    float* out = (float*)d_out;                 // (512, 5, 20, 20, 20)

    h_build_tables();
    cudaMemcpyToSymbolAsync(TAB_d, host_tab, sizeof(float) * TAB_LEN, 0,
                            cudaMemcpyHostToDevice, 0);

    k_fhat<<<1024, 128>>>(x);
    dim3 g(512, 5);
    k_main<<<g, 256>>>(kern, bias, out);
}